// round 10
// baseline (speedup 1.0000x reference)
#include <cuda_runtime.h>

// Problem constants (fixed shapes: B=1, C=1, H=W=96)
#define NN       9216
#define WW       96
#define INV_SXY  (1.0f / 15.0f)
#define SRGB_SCL 8.0f
#define LOG2E    1.4426950408889634f
#define NHL2E    (-0.7213475204444817f)   // -0.5 * log2(e)

// 48x48 grid of 192x192 tiles -> 1176 tile-pairs; each split into 2 blocks
// whose j-range is ONE image row (96 px = 48 pairs) so dy is a per-block
// constant folded into the i-side bias. 2352 blocks x 2 warps ~ 32 warps/SM.
#define NB      48
#define TILE    192            // NN / NB
#define NPAIR   (TILE / 2)     // 96 j-pairs per tile
#define JROW    48             // j-pairs per block = one image row
#define TPB     64
#define IPT     3              // TPB * IPT == TILE
#define NTPAIRS (NB * (NB + 1) / 2)   // 1176
#define NBLOCKS (NTPAIRS * 2)         // 2352

// ---- f32x2 helpers (sm_103a packed fp32 pipe; ptxas won't auto-fuse) ----
typedef unsigned long long u64;
__device__ __forceinline__ u64 pack2(float lo, float hi) {
    u64 r; asm("mov.b64 %0, {%1,%2};" : "=l"(r) : "f"(lo), "f"(hi)); return r;
}
__device__ __forceinline__ void unpack2(u64 v, float& lo, float& hi) {
    asm("mov.b64 {%0,%1}, %2;" : "=f"(lo), "=f"(hi) : "l"(v));
}
__device__ __forceinline__ u64 fma2(u64 a, u64 b, u64 c) {
    u64 r; asm("fma.rn.f32x2 %0, %1, %2, %3;" : "=l"(r) : "l"(a), "l"(b), "l"(c)); return r;
}
__device__ __forceinline__ u64 add2(u64 a, u64 b) {
    u64 r; asm("add.rn.f32x2 %0, %1, %2;" : "=l"(r) : "l"(a), "l"(b)); return r;
}
__device__ __forceinline__ float ex2f(float a) {
    float w; asm("ex2.approx.ftz.f32 %0, %1;" : "=f"(w) : "f"(a)); return w;
}

// i-side per pixel: {L2E*fr, L2E*fg, L2E*fb, NHL2E*|frgb|^2}, f = 8*rgb
__device__ float4 g_iA[NN];
__device__ float  g_is[NN];
// j-side pair-packed (pair p = pixels 2p,2p+1); each 16B = two f32x2 operands:
// q0 = {fx0,fx1 | fr0,fr1}   q1 = {fg0,fg1 | fb0,fb1}
// q2 = {bj0,bj1 | t0, t1 }   q3 = {s0, s1  | p0, p1 }   (b=NHL2E*(fx^2+|frgb|^2),
//                                                        t=1-s, p=1-2s)
__device__ float4 g_q0[NN / 2];
__device__ float4 g_q1[NN / 2];
__device__ float4 g_q2[NN / 2];
__device__ float4 g_q3[NN / 2];

__global__ void precompute_kernel(const float* __restrict__ inp,
                                  const float* __restrict__ img,
                                  float* __restrict__ out, int out_size) {
    int p = blockIdx.x * blockDim.x + threadIdx.x;
    if (p < out_size) out[p] = 0.0f;           // fused output zeroing
    if (p >= NN / 2) return;
    float fx[2], fr[2], fg[2], fb[2], bj[2], tt[2], ss[2], pp[2];
#pragma unroll
    for (int l = 0; l < 2; l++) {
        int n = 2 * p + l;
        float x = (float)(n % WW) * INV_SXY;
        float r = img[n]          * SRGB_SCL;
        float g = img[NN + n]     * SRGB_SCL;
        float b = img[2 * NN + n] * SRGB_SCL;
        float s = inp[n];
        fx[l] = x; fr[l] = r; fg[l] = g; fb[l] = b;
        bj[l] = NHL2E * (x * x + r * r + g * g + b * b);
        tt[l] = 1.0f - s; ss[l] = s; pp[l] = fmaf(-2.0f, s, 1.0f);
        g_iA[n] = make_float4(LOG2E * r, LOG2E * g, LOG2E * b,
                              NHL2E * (r * r + g * g + b * b));
        g_is[n] = s;
    }
    g_q0[p] = make_float4(fx[0], fx[1], fr[0], fr[1]);
    g_q1[p] = make_float4(fg[0], fg[1], fb[0], fb[1]);
    g_q2[p] = make_float4(bj[0], bj[1], tt[0], tt[1]);
    g_q3[p] = make_float4(ss[0], ss[1], pp[0], pp[1]);
}

// w_ij = 2^( a_i + b_j + Fx*gx + Fr*gr + Fg*gg + Fb*gb ) = exp(-0.5*d2)
// 3-stage software pipeline over jj: at iteration jj we
//   (A) accumulate w(jj-2),  (B) EX2 arg(jj-1),  (C) build arg(jj).
// Every RAW dependency spans a full jj-iteration (~36 issue slots), so the
// loop runs at pipe-throughput, not chain-latency.
__global__ __launch_bounds__(TPB)
void crf_main_kernel(float* __restrict__ out) {
    __shared__ ulonglong2 sQ0[JROW], sQ1[JROW], sQ2[JROW], sQ3[JROW];
    __shared__ float      sred[TPB / 32];

    // blockIdx -> (tile-pair, j-row); decode pair -> (bi, bj), bi <= bj
    int bp   = blockIdx.x >> 1;
    int half = blockIdx.x & 1;
    int bi = 0;
    while (bp >= NB - bi) { bp -= NB - bi; bi++; }
    int bj = bi + bp;

    const int t  = threadIdx.x;
    const int i0 = bi * TILE;
    const int jp = bj * NPAIR + half * JROW;    // j-pair base (one image row)
    const int yj = 2 * bj + half;               // fixed j row

    const ulonglong2* __restrict__ gq0 = (const ulonglong2*)g_q0;
    const ulonglong2* __restrict__ gq1 = (const ulonglong2*)g_q1;
    const ulonglong2* __restrict__ gq2 = (const ulonglong2*)g_q2;
    const ulonglong2* __restrict__ gq3 = (const ulonglong2*)g_q3;
    for (int k = t; k < JROW; k += TPB) {
        sQ0[k] = gq0[jp + k];
        sQ1[k] = gq1[jp + k];
        sQ2[k] = gq2[jp + k];
        sQ3[k] = gq3[jp + k];
    }

    // per-thread i state (broadcast-packed, loop-invariant)
    u64 FX[IPT], FR[IPT], FG[IPT], FB[IPT], A2[IPT];
    float si[IPT], acc0[IPT], acc1[IPT];
#pragma unroll
    for (int u = 0; u < IPT; u++) {
        int li = u * TPB + t;                   // 0..191 within tile
        int xi = (li >= WW) ? li - WW : li;
        int yi = 2 * bi + (li >= WW);
        float4 A = g_iA[i0 + li];
        float  s = g_is[i0 + li];
        float fxi = (float)xi * INV_SXY;
        float dy  = (float)(yi - yj) * INV_SXY;
        float a   = A.w + NHL2E * (fxi * fxi + dy * dy);
        FX[u] = pack2(LOG2E * fxi, LOG2E * fxi);
        FR[u] = pack2(A.x, A.x);
        FG[u] = pack2(A.y, A.y);
        FB[u] = pack2(A.z, A.z);
        A2[u] = pack2(a, a);
        si[u] = s; acc0[u] = 0.0f; acc1[u] = 0.0f;
    }
    __syncthreads();

    u64   argP[IPT];            // arg(jj-1), awaiting EX2
    float w0A[IPT], w1A[IPT];   // w(jj-2), awaiting accumulate

#define BUILD_ARG(u)                               \
    do { u64 arg = add2(A2[u], B2);                \
         arg = fma2(FX[u], Gx, arg);               \
         arg = fma2(FR[u], Gr, arg);               \
         arg = fma2(FG[u], Gg, arg);               \
         argP[u] = fma2(FB[u], Gb, arg); } while (0)

    if (bi == bj) {
        float ta0, ta1, tb0, tb1;               // t(jj-2), t(jj-1)
        {   // jj = 0: build only
            ulonglong2 Q0 = sQ0[0], Q1 = sQ1[0], Q2 = sQ2[0];
            u64 Gx = Q0.x, Gr = Q0.y, Gg = Q1.x, Gb = Q1.y, B2 = Q2.x;
            unpack2(Q2.y, ta0, ta1);
#pragma unroll
            for (int u = 0; u < IPT; u++) BUILD_ARG(u);
        }
        {   // jj = 1: EX2(0) + build(1)
            ulonglong2 Q0 = sQ0[1], Q1 = sQ1[1], Q2 = sQ2[1];
            u64 Gx = Q0.x, Gr = Q0.y, Gg = Q1.x, Gb = Q1.y, B2 = Q2.x;
            unpack2(Q2.y, tb0, tb1);
#pragma unroll
            for (int u = 0; u < IPT; u++) {
                float a0, a1; unpack2(argP[u], a0, a1);
                w0A[u] = ex2f(a0); w1A[u] = ex2f(a1);
                BUILD_ARG(u);
            }
        }
#pragma unroll 2
        for (int jj = 2; jj < JROW; jj++) {
            ulonglong2 Q0 = sQ0[jj], Q1 = sQ1[jj], Q2 = sQ2[jj];
            u64 Gx = Q0.x, Gr = Q0.y, Gg = Q1.x, Gb = Q1.y, B2 = Q2.x;
            float tc0, tc1; unpack2(Q2.y, tc0, tc1);
#pragma unroll
            for (int u = 0; u < IPT; u++) {
                acc0[u] = fmaf(w0A[u], ta0, acc0[u]);   // A: accumulate jj-2
                acc1[u] = fmaf(w1A[u], ta1, acc1[u]);
                float a0, a1; unpack2(argP[u], a0, a1); // B: EX2 jj-1
                w0A[u] = ex2f(a0); w1A[u] = ex2f(a1);
                BUILD_ARG(u);                           // C: build jj
            }
            ta0 = tb0; ta1 = tb1; tb0 = tc0; tb1 = tc1;
        }
        // epilogue: drain the two in-flight stages
#pragma unroll
        for (int u = 0; u < IPT; u++) {
            acc0[u] = fmaf(w0A[u], ta0, acc0[u]);
            acc1[u] = fmaf(w1A[u], ta1, acc1[u]);
            float a0, a1; unpack2(argP[u], a0, a1);
            acc0[u] = fmaf(ex2f(a0), tb0, acc0[u]);
            acc1[u] = fmaf(ex2f(a1), tb1, acc1[u]);
        }
    } else {
        float sa0, sa1, pa0, pa1;               // s,p of jj-2
        float sb0, sb1, pb0, pb1;               // s,p of jj-1
        {   // jj = 0: build only
            ulonglong2 Q0 = sQ0[0], Q1 = sQ1[0], Q2 = sQ2[0], Q3 = sQ3[0];
            u64 Gx = Q0.x, Gr = Q0.y, Gg = Q1.x, Gb = Q1.y, B2 = Q2.x;
            unpack2(Q3.x, sa0, sa1); unpack2(Q3.y, pa0, pa1);
#pragma unroll
            for (int u = 0; u < IPT; u++) BUILD_ARG(u);
        }
        {   // jj = 1: EX2(0) + build(1)
            ulonglong2 Q0 = sQ0[1], Q1 = sQ1[1], Q2 = sQ2[1], Q3 = sQ3[1];
            u64 Gx = Q0.x, Gr = Q0.y, Gg = Q1.x, Gb = Q1.y, B2 = Q2.x;
            unpack2(Q3.x, sb0, sb1); unpack2(Q3.y, pb0, pb1);
#pragma unroll
            for (int u = 0; u < IPT; u++) {
                float a0, a1; unpack2(argP[u], a0, a1);
                w0A[u] = ex2f(a0); w1A[u] = ex2f(a1);
                BUILD_ARG(u);
            }
        }
#pragma unroll 2
        for (int jj = 2; jj < JROW; jj++) {
            ulonglong2 Q0 = sQ0[jj], Q1 = sQ1[jj], Q2 = sQ2[jj], Q3 = sQ3[jj];
            u64 Gx = Q0.x, Gr = Q0.y, Gg = Q1.x, Gb = Q1.y, B2 = Q2.x;
            float sc0, sc1, pc0, pc1;
            unpack2(Q3.x, sc0, sc1); unpack2(Q3.y, pc0, pc1);
#pragma unroll
            for (int u = 0; u < IPT; u++) {
                float c0 = fmaf(si[u], pa0, sa0);       // s_i + s_j - 2 s_i s_j
                float c1 = fmaf(si[u], pa1, sa1);
                acc0[u] = fmaf(w0A[u], c0, acc0[u]);    // A: accumulate jj-2
                acc1[u] = fmaf(w1A[u], c1, acc1[u]);
                float a0, a1; unpack2(argP[u], a0, a1); // B: EX2 jj-1
                w0A[u] = ex2f(a0); w1A[u] = ex2f(a1);
                BUILD_ARG(u);                           // C: build jj
            }
            sa0 = sb0; sa1 = sb1; pa0 = pb0; pa1 = pb1;
            sb0 = sc0; sb1 = sc1; pb0 = pc0; pb1 = pc1;
        }
        // epilogue
#pragma unroll
        for (int u = 0; u < IPT; u++) {
            float c0 = fmaf(si[u], pa0, sa0);
            float c1 = fmaf(si[u], pa1, sa1);
            acc0[u] = fmaf(w0A[u], c0, acc0[u]);
            acc1[u] = fmaf(w1A[u], c1, acc1[u]);
            float a0, a1; unpack2(argP[u], a0, a1);
            float d0 = fmaf(si[u], pb0, sb0);
            float d1 = fmaf(si[u], pb1, sb1);
            acc0[u] = fmaf(ex2f(a0), d0, acc0[u]);
            acc1[u] = fmaf(ex2f(a1), d1, acc1[u]);
        }
    }
#undef BUILD_ARG

    float tot = 0.0f;
    if (bi == bj) {
#pragma unroll
        for (int u = 0; u < IPT; u++) tot = fmaf(si[u], acc0[u] + acc1[u], tot);
    } else {
#pragma unroll
        for (int u = 0; u < IPT; u++) tot += acc0[u] + acc1[u];
    }
    tot *= (1.0f / (float)NN);

    // Block reduce: warp shuffle then smem (TPB = 64 -> 2 warps)
#pragma unroll
    for (int off = 16; off > 0; off >>= 1)
        tot += __shfl_xor_sync(0xFFFFFFFFu, tot, off);
    if ((t & 31) == 0) sred[t >> 5] = tot;
    __syncthreads();
    if (t == 0) atomicAdd(out, sred[0] + sred[1]);
}

extern "C" void kernel_launch(void* const* d_in, const int* in_sizes, int n_in,
                              void* d_out, int out_size) {
    const float* inp = (const float*)d_in[0];   // [1,1,96,96] seg probs
    const float* img = (const float*)d_in[1];   // [1,3,96,96] rgb
    float* out = (float*)d_out;

    precompute_kernel<<<(NN / 2 + 255) / 256, 256>>>(inp, img, out, out_size);
    crf_main_kernel<<<NBLOCKS, TPB>>>(out);
}

// round 13
// speedup vs baseline: 1.0311x; 1.0311x over previous
#include <cuda_runtime.h>

// Problem constants (fixed shapes: B=1, C=1, H=W=96)
#define NN       9216
#define WW       96
#define INV_SXY  (1.0f / 15.0f)
#define SRGB_SCL 8.0f
#define LOG2E    1.4426950408889634f
#define NHL2E    (-0.7213475204444817f)   // -0.5 * log2(e)

// 48x48 grid of 192x192 tiles -> 1176 tile-pairs; each split into 2 blocks
// whose j-range is ONE image row (96 px = 48 pairs) so dy is a per-block
// constant folded into the i-side bias. 2352 blocks x 2 warps ~ 32 warps/SM.
#define NB      48
#define TILE    192            // NN / NB
#define NPAIR   (TILE / 2)     // 96 j-pairs per tile
#define JROW    48             // j-pairs per block = one image row
#define TPB     64
#define IPT     3              // TPB * IPT == TILE
#define NTPAIRS (NB * (NB + 1) / 2)   // 1176
#define NBLOCKS (NTPAIRS * 2)         // 2352

// ---- f32x2 helpers (sm_103a packed fp32 pipe; ptxas won't auto-fuse) ----
typedef unsigned long long u64;
__device__ __forceinline__ u64 pack2(float lo, float hi) {
    u64 r; asm("mov.b64 %0, {%1,%2};" : "=l"(r) : "f"(lo), "f"(hi)); return r;
}
__device__ __forceinline__ void unpack2(u64 v, float& lo, float& hi) {
    asm("mov.b64 {%0,%1}, %2;" : "=f"(lo), "=f"(hi) : "l"(v));
}
__device__ __forceinline__ u64 fma2(u64 a, u64 b, u64 c) {
    u64 r; asm("fma.rn.f32x2 %0, %1, %2, %3;" : "=l"(r) : "l"(a), "l"(b), "l"(c)); return r;
}
__device__ __forceinline__ u64 add2(u64 a, u64 b) {
    u64 r; asm("add.rn.f32x2 %0, %1, %2;" : "=l"(r) : "l"(a), "l"(b)); return r;
}
__device__ __forceinline__ float ex2f(float a) {
    float w; asm("ex2.approx.ftz.f32 %0, %1;" : "=f"(w) : "f"(a)); return w;
}

// i-side per pixel: {L2E*fr, L2E*fg, L2E*fb, NHL2E*|frgb|^2}, f = 8*rgb
__device__ float4 g_iA[NN];
__device__ float  g_is[NN];
// j-side pair-packed (pair p = pixels 2p,2p+1); each 16B = two f32x2 operands:
// q0 = {fx0,fx1 | fr0,fr1}   q1 = {fg0,fg1 | fb0,fb1}
// q2 = {bj0,bj1 | p0, p1 }   b = NHL2E*(fx^2+|frgb|^2), p = 1-2s
// (t = 1-s = (1+p)/2 and s = (1-p)/2 are derived from p; no 4th array.)
__device__ float4 g_q0[NN / 2];
__device__ float4 g_q1[NN / 2];
__device__ float4 g_q2[NN / 2];

__global__ void precompute_kernel(const float* __restrict__ inp,
                                  const float* __restrict__ img,
                                  float* __restrict__ out, int out_size) {
    int p = blockIdx.x * blockDim.x + threadIdx.x;
    if (p < out_size) out[p] = 0.0f;           // fused output zeroing
    if (p >= NN / 2) return;
    float fx[2], fr[2], fg[2], fb[2], bj[2], pp[2];
#pragma unroll
    for (int l = 0; l < 2; l++) {
        int n = 2 * p + l;
        float x = (float)(n % WW) * INV_SXY;
        float r = img[n]          * SRGB_SCL;
        float g = img[NN + n]     * SRGB_SCL;
        float b = img[2 * NN + n] * SRGB_SCL;
        float s = inp[n];
        fx[l] = x; fr[l] = r; fg[l] = g; fb[l] = b;
        bj[l] = NHL2E * (x * x + r * r + g * g + b * b);
        pp[l] = fmaf(-2.0f, s, 1.0f);
        g_iA[n] = make_float4(LOG2E * r, LOG2E * g, LOG2E * b,
                              NHL2E * (r * r + g * g + b * b));
        g_is[n] = s;
    }
    g_q0[p] = make_float4(fx[0], fx[1], fr[0], fr[1]);
    g_q1[p] = make_float4(fg[0], fg[1], fb[0], fb[1]);
    g_q2[p] = make_float4(bj[0], bj[1], pp[0], pp[1]);
}

// w_ij = 2^( a_i + b_j + Fx*gx + Fr*gr + Fg*gg + Fb*gb ) = exp(-0.5*d2)
//   a_i includes rgb self-energy + xi^2 + dy^2 (dy const per block).
// Diagonal tile-pairs: acc += w*t_j,  t_j = (1+p_j)/2, then * s_i
// Off-diag tile-pairs: acc += w*c,    c = fmaf(p_j, s_i-0.5, 0.5)
//                      (= s_i + s_j - 2 s_i s_j; covers both orders)
// 2-stage deferral: EX2+acc of iteration jj-1 runs inside iteration jj,
// interleaved with its FFMA2 build chain.
__global__ __launch_bounds__(TPB)
void crf_main_kernel(float* __restrict__ out) {
    __shared__ ulonglong2 sQ0[JROW], sQ1[JROW], sQ2[JROW];
    __shared__ float      sred[TPB / 32];

    // blockIdx -> (tile-pair, j-row); decode pair -> (bi, bj), bi <= bj
    int bp   = blockIdx.x >> 1;
    int half = blockIdx.x & 1;
    int bi = 0;
    while (bp >= NB - bi) { bp -= NB - bi; bi++; }
    int bj = bi + bp;

    const int t  = threadIdx.x;
    const int i0 = bi * TILE;
    const int jp = bj * NPAIR + half * JROW;    // j-pair base (one image row)
    const int yj = 2 * bj + half;               // fixed j row

    const ulonglong2* __restrict__ gq0 = (const ulonglong2*)g_q0;
    const ulonglong2* __restrict__ gq1 = (const ulonglong2*)g_q1;
    const ulonglong2* __restrict__ gq2 = (const ulonglong2*)g_q2;
    for (int k = t; k < JROW; k += TPB) {
        sQ0[k] = gq0[jp + k];
        sQ1[k] = gq1[jp + k];
        sQ2[k] = gq2[jp + k];
    }

    // per-thread i state (broadcast-packed, loop-invariant)
    u64 FX[IPT], FR[IPT], FG[IPT], FB[IPT], A2[IPT];
    float si[IPT], sih[IPT], acc0[IPT], acc1[IPT];
#pragma unroll
    for (int u = 0; u < IPT; u++) {
        int li = u * TPB + t;                   // 0..191 within tile
        int xi = (li >= WW) ? li - WW : li;
        int yi = 2 * bi + (li >= WW);
        float4 A = g_iA[i0 + li];
        float  s = g_is[i0 + li];
        float fxi = (float)xi * INV_SXY;
        float dy  = (float)(yi - yj) * INV_SXY;
        float a   = A.w + NHL2E * (fxi * fxi + dy * dy);
        FX[u] = pack2(LOG2E * fxi, LOG2E * fxi);
        FR[u] = pack2(A.x, A.x);
        FG[u] = pack2(A.y, A.y);
        FB[u] = pack2(A.z, A.z);
        A2[u] = pack2(a, a);
        si[u] = s; sih[u] = s - 0.5f;
        acc0[u] = 0.0f; acc1[u] = 0.0f;
    }
    __syncthreads();

    u64 argP[IPT];                              // pending args (iter jj-1)

#define BUILD_ARG(u)                               \
    do { u64 arg = add2(A2[u], B2);                \
         arg = fma2(FX[u], Gx, arg);               \
         arg = fma2(FR[u], Gr, arg);               \
         arg = fma2(FG[u], Gg, arg);               \
         argP[u] = fma2(FB[u], Gb, arg); } while (0)

    if (bi == bj) {
        float t0p, t1p;                         // pending coeffs t=(1+p)/2
        {   // jj = 0: build only
            ulonglong2 Q0 = sQ0[0], Q1 = sQ1[0], Q2 = sQ2[0];
            u64 Gx = Q0.x, Gr = Q0.y, Gg = Q1.x, Gb = Q1.y, B2 = Q2.x;
            float p0, p1; unpack2(Q2.y, p0, p1);
            t0p = fmaf(0.5f, p0, 0.5f); t1p = fmaf(0.5f, p1, 0.5f);
#pragma unroll
            for (int u = 0; u < IPT; u++) BUILD_ARG(u);
        }
#pragma unroll 4
        for (int jj = 1; jj < JROW; jj++) {
            ulonglong2 Q0 = sQ0[jj], Q1 = sQ1[jj], Q2 = sQ2[jj];
            u64 Gx = Q0.x, Gr = Q0.y, Gg = Q1.x, Gb = Q1.y, B2 = Q2.x;
            float p0, p1; unpack2(Q2.y, p0, p1);
            float t0c = fmaf(0.5f, p0, 0.5f), t1c = fmaf(0.5f, p1, 0.5f);
#pragma unroll
            for (int u = 0; u < IPT; u++) {
                float a0, a1; unpack2(argP[u], a0, a1);
                float w0 = ex2f(a0), w1 = ex2f(a1);
                acc0[u] = fmaf(w0, t0p, acc0[u]);
                acc1[u] = fmaf(w1, t1p, acc1[u]);
                BUILD_ARG(u);
            }
            t0p = t0c; t1p = t1c;
        }
#pragma unroll
        for (int u = 0; u < IPT; u++) {         // retire last iteration
            float a0, a1; unpack2(argP[u], a0, a1);
            acc0[u] = fmaf(ex2f(a0), t0p, acc0[u]);
            acc1[u] = fmaf(ex2f(a1), t1p, acc1[u]);
        }
    } else {
        float p0p, p1p;                         // pending p_j
        {   // jj = 0: build only
            ulonglong2 Q0 = sQ0[0], Q1 = sQ1[0], Q2 = sQ2[0];
            u64 Gx = Q0.x, Gr = Q0.y, Gg = Q1.x, Gb = Q1.y, B2 = Q2.x;
            unpack2(Q2.y, p0p, p1p);
#pragma unroll
            for (int u = 0; u < IPT; u++) BUILD_ARG(u);
        }
#pragma unroll 4
        for (int jj = 1; jj < JROW; jj++) {
            ulonglong2 Q0 = sQ0[jj], Q1 = sQ1[jj], Q2 = sQ2[jj];
            u64 Gx = Q0.x, Gr = Q0.y, Gg = Q1.x, Gb = Q1.y, B2 = Q2.x;
            float p0c, p1c; unpack2(Q2.y, p0c, p1c);
#pragma unroll
            for (int u = 0; u < IPT; u++) {
                float a0, a1; unpack2(argP[u], a0, a1);
                float w0 = ex2f(a0), w1 = ex2f(a1);
                float c0 = fmaf(p0p, sih[u], 0.5f);  // s_i+s_j-2 s_i s_j
                float c1 = fmaf(p1p, sih[u], 0.5f);
                acc0[u] = fmaf(w0, c0, acc0[u]);
                acc1[u] = fmaf(w1, c1, acc1[u]);
                BUILD_ARG(u);
            }
            p0p = p0c; p1p = p1c;
        }
#pragma unroll
        for (int u = 0; u < IPT; u++) {         // retire last iteration
            float a0, a1; unpack2(argP[u], a0, a1);
            float c0 = fmaf(p0p, sih[u], 0.5f);
            float c1 = fmaf(p1p, sih[u], 0.5f);
            acc0[u] = fmaf(ex2f(a0), c0, acc0[u]);
            acc1[u] = fmaf(ex2f(a1), c1, acc1[u]);
        }
    }
#undef BUILD_ARG

    float tot = 0.0f;
    if (bi == bj) {
#pragma unroll
        for (int u = 0; u < IPT; u++) tot = fmaf(si[u], acc0[u] + acc1[u], tot);
    } else {
#pragma unroll
        for (int u = 0; u < IPT; u++) tot += acc0[u] + acc1[u];
    }
    tot *= (1.0f / (float)NN);

    // Block reduce: warp shuffle then smem (TPB = 64 -> 2 warps)
#pragma unroll
    for (int off = 16; off > 0; off >>= 1)
        tot += __shfl_xor_sync(0xFFFFFFFFu, tot, off);
    if ((t & 31) == 0) sred[t >> 5] = tot;
    __syncthreads();
    if (t == 0) atomicAdd(out, sred[0] + sred[1]);
}

extern "C" void kernel_launch(void* const* d_in, const int* in_sizes, int n_in,
                              void* d_out, int out_size) {
    const float* inp = (const float*)d_in[0];   // [1,1,96,96] seg probs
    const float* img = (const float*)d_in[1];   // [1,3,96,96] rgb
    float* out = (float*)d_out;

    precompute_kernel<<<(NN / 2 + 255) / 256, 256>>>(inp, img, out, out_size);
    crf_main_kernel<<<NBLOCKS, TPB>>>(out);
}

// round 16
// speedup vs baseline: 1.0887x; 1.0558x over previous
#include <cuda_runtime.h>

// Problem constants (fixed shapes: B=1, C=1, H=W=96)
#define NN       9216
#define WW       96
#define INV_SXY  (1.0f / 15.0f)
#define SRGB_SCL 8.0f
#define LOG2E    1.4426950408889634f
#define NHL2E    (-0.7213475204444817f)   // -0.5 * log2(e)

// 48x48 grid of 192x192 tiles -> 1176 tile-pairs; each split into 2 blocks
// whose j-range is ONE image row (96 px = 48 pairs) so dy is a per-block
// constant folded into the i-side bias. 2352 blocks x 2 warps ~ 32 warps/SM.
#define NB      48
#define TILE    192            // NN / NB
#define NPAIR   (TILE / 2)     // 96 j-pairs per tile
#define JROW    48             // j-pairs per block = one image row
#define TPB     64
#define IPT     3              // TPB * IPT == TILE
#define NTPAIRS (NB * (NB + 1) / 2)   // 1176
#define NBLOCKS (NTPAIRS * 2)         // 2352

// ---- f32x2 helpers (sm_103a packed fp32 pipe; ptxas won't auto-fuse) ----
typedef unsigned long long u64;
__device__ __forceinline__ u64 pack2(float lo, float hi) {
    u64 r; asm("mov.b64 %0, {%1,%2};" : "=l"(r) : "f"(lo), "f"(hi)); return r;
}
__device__ __forceinline__ void unpack2(u64 v, float& lo, float& hi) {
    asm("mov.b64 {%0,%1}, %2;" : "=f"(lo), "=f"(hi) : "l"(v));
}
__device__ __forceinline__ u64 fma2(u64 a, u64 b, u64 c) {
    u64 r; asm("fma.rn.f32x2 %0, %1, %2, %3;" : "=l"(r) : "l"(a), "l"(b), "l"(c)); return r;
}
__device__ __forceinline__ u64 add2(u64 a, u64 b) {
    u64 r; asm("add.rn.f32x2 %0, %1, %2;" : "=l"(r) : "l"(a), "l"(b)); return r;
}
__device__ __forceinline__ float ex2f(float a) {
    float w; asm("ex2.approx.ftz.f32 %0, %1;" : "=f"(w) : "f"(a)); return w;
}

// i-side per pixel: {L2E*fr, L2E*fg, L2E*fb, NHL2E*|frgb|^2}, f = 8*rgb
__device__ float4 g_iA[NN];
__device__ float  g_is[NN];
// j-side pair-packed (pair p = pixels 2p,2p+1); each 16B = two f32x2 operands:
// q0 = {fx0,fx1 | fr0,fr1}   q1 = {fg0,fg1 | fb0,fb1}
// q2 = {bj0,bj1 | p0, p1 }   b = NHL2E*(fx^2+|frgb|^2), p = 1-2s
__device__ float4 g_q0[NN / 2];
__device__ float4 g_q1[NN / 2];
__device__ float4 g_q2[NN / 2];

__global__ void precompute_kernel(const float* __restrict__ inp,
                                  const float* __restrict__ img,
                                  float* __restrict__ out, int out_size) {
    int p = blockIdx.x * blockDim.x + threadIdx.x;
    if (p < out_size) out[p] = 0.0f;           // fused output zeroing
    if (p >= NN / 2) return;
    float fx[2], fr[2], fg[2], fb[2], bj[2], pp[2];
#pragma unroll
    for (int l = 0; l < 2; l++) {
        int n = 2 * p + l;
        float x = (float)(n % WW) * INV_SXY;
        float r = img[n]          * SRGB_SCL;
        float g = img[NN + n]     * SRGB_SCL;
        float b = img[2 * NN + n] * SRGB_SCL;
        float s = inp[n];
        fx[l] = x; fr[l] = r; fg[l] = g; fb[l] = b;
        bj[l] = NHL2E * (x * x + r * r + g * g + b * b);
        pp[l] = fmaf(-2.0f, s, 1.0f);
        g_iA[n] = make_float4(LOG2E * r, LOG2E * g, LOG2E * b,
                              NHL2E * (r * r + g * g + b * b));
        g_is[n] = s;
    }
    g_q0[p] = make_float4(fx[0], fx[1], fr[0], fr[1]);
    g_q1[p] = make_float4(fg[0], fg[1], fb[0], fb[1]);
    g_q2[p] = make_float4(bj[0], bj[1], pp[0], pp[1]);
}

// w_ij = 2^( a_i + b_j + Fx*gx + Fr*gr + Fg*gg + Fb*gb ) = exp(-0.5*d2)
// Dual accumulators in the (identical for diag/off-diag) inner loop:
//   accW  += {w0,w1}            accWP += {w0*p_j0, w1*p_j1}
// Epilogue only differs:
//   diag (t=(1+p)/2):  tot += s_i * 0.5*(SumW + SumWP)
//   off  (c=0.5+p*sih): tot += 0.5*SumW + sih_i*SumWP   (covers both orders)
// jj body ordered [EX2(jj-1)] -> [build arg(jj)] -> [accumulate(jj-1)] so the
// MUFU->FFMA RAW spans ~20 issue slots.
__global__ __launch_bounds__(TPB, 16)
void crf_main_kernel(float* __restrict__ out) {
    __shared__ ulonglong2 sQ0[JROW], sQ1[JROW], sQ2[JROW];
    __shared__ float      sred[TPB / 32];

    // blockIdx -> (tile-pair, j-row); decode pair -> (bi, bj), bi <= bj
    int bp   = blockIdx.x >> 1;
    int half = blockIdx.x & 1;
    int bi = 0;
    while (bp >= NB - bi) { bp -= NB - bi; bi++; }
    int bj = bi + bp;

    const int t  = threadIdx.x;
    const int i0 = bi * TILE;
    const int jp = bj * NPAIR + half * JROW;    // j-pair base (one image row)
    const int yj = 2 * bj + half;               // fixed j row

    const ulonglong2* __restrict__ gq0 = (const ulonglong2*)g_q0;
    const ulonglong2* __restrict__ gq1 = (const ulonglong2*)g_q1;
    const ulonglong2* __restrict__ gq2 = (const ulonglong2*)g_q2;
    for (int k = t; k < JROW; k += TPB) {
        sQ0[k] = gq0[jp + k];
        sQ1[k] = gq1[jp + k];
        sQ2[k] = gq2[jp + k];
    }

    // per-thread i state (broadcast-packed, loop-invariant)
    u64 FX[IPT], FR[IPT], FG[IPT], FB[IPT], A2[IPT];
    u64 accW[IPT], accWP[IPT];
    float sih[IPT];
#pragma unroll
    for (int u = 0; u < IPT; u++) {
        int li = u * TPB + t;                   // 0..191 within tile
        int xi = (li >= WW) ? li - WW : li;
        int yi = 2 * bi + (li >= WW);
        float4 A = g_iA[i0 + li];
        float  s = g_is[i0 + li];
        float fxi = (float)xi * INV_SXY;
        float dy  = (float)(yi - yj) * INV_SXY;
        float a   = A.w + NHL2E * (fxi * fxi + dy * dy);
        FX[u] = pack2(LOG2E * fxi, LOG2E * fxi);
        FR[u] = pack2(A.x, A.x);
        FG[u] = pack2(A.y, A.y);
        FB[u] = pack2(A.z, A.z);
        A2[u] = pack2(a, a);
        sih[u] = s - 0.5f;
        accW[u] = 0ull; accWP[u] = 0ull;
    }
    __syncthreads();

    u64 argP[IPT];      // arg(jj-1), awaiting EX2
    u64 P2p;            // p-pair of jj-1 (raw smem u64, used by accWP)

#define BUILD_ARG(u)                               \
    do { u64 arg = add2(A2[u], B2);                \
         arg = fma2(FX[u], Gx, arg);               \
         arg = fma2(FR[u], Gr, arg);               \
         arg = fma2(FG[u], Gg, arg);               \
         argP[u] = fma2(FB[u], Gb, arg); } while (0)

    {   // jj = 0: build only
        ulonglong2 Q0 = sQ0[0], Q1 = sQ1[0], Q2 = sQ2[0];
        u64 Gx = Q0.x, Gr = Q0.y, Gg = Q1.x, Gb = Q1.y, B2 = Q2.x;
        P2p = Q2.y;
#pragma unroll
        for (int u = 0; u < IPT; u++) BUILD_ARG(u);
    }
#pragma unroll 4
    for (int jj = 1; jj < JROW; jj++) {
        ulonglong2 Q0 = sQ0[jj], Q1 = sQ1[jj], Q2 = sQ2[jj];
        u64 Gx = Q0.x, Gr = Q0.y, Gg = Q1.x, Gb = Q1.y, B2 = Q2.x;
        u64 P2c = Q2.y;
        // stage B: EX2 of arg(jj-1)
        float w0[IPT], w1[IPT];
#pragma unroll
        for (int u = 0; u < IPT; u++) {
            float a0, a1; unpack2(argP[u], a0, a1);
            w0[u] = ex2f(a0); w1[u] = ex2f(a1);
        }
        // stage C: build arg(jj)  (fills the MUFU latency window)
#pragma unroll
        for (int u = 0; u < IPT; u++) BUILD_ARG(u);
        // stage A: accumulate (jj-1)
#pragma unroll
        for (int u = 0; u < IPT; u++) {
            u64 W2 = pack2(w0[u], w1[u]);
            accW[u]  = add2(accW[u], W2);
            accWP[u] = fma2(W2, P2p, accWP[u]);
        }
        P2p = P2c;
    }
    // drain last iteration
#pragma unroll
    for (int u = 0; u < IPT; u++) {
        float a0, a1; unpack2(argP[u], a0, a1);
        u64 W2 = pack2(ex2f(a0), ex2f(a1));
        accW[u]  = add2(accW[u], W2);
        accWP[u] = fma2(W2, P2p, accWP[u]);
    }
#undef BUILD_ARG

    float tot = 0.0f;
    if (bi == bj) {
#pragma unroll
        for (int u = 0; u < IPT; u++) {
            float aw0, aw1, ap0, ap1;
            unpack2(accW[u],  aw0, aw1);
            unpack2(accWP[u], ap0, ap1);
            float si = sih[u] + 0.5f;
            tot = fmaf(si, 0.5f * (aw0 + aw1 + ap0 + ap1), tot);
        }
    } else {
#pragma unroll
        for (int u = 0; u < IPT; u++) {
            float aw0, aw1, ap0, ap1;
            unpack2(accW[u],  aw0, aw1);
            unpack2(accWP[u], ap0, ap1);
            tot += 0.5f * (aw0 + aw1) + sih[u] * (ap0 + ap1);
        }
    }
    tot *= (1.0f / (float)NN);

    // Block reduce: warp shuffle then smem (TPB = 64 -> 2 warps)
#pragma unroll
    for (int off = 16; off > 0; off >>= 1)
        tot += __shfl_xor_sync(0xFFFFFFFFu, tot, off);
    if ((t & 31) == 0) sred[t >> 5] = tot;
    __syncthreads();
    if (t == 0) atomicAdd(out, sred[0] + sred[1]);
}

extern "C" void kernel_launch(void* const* d_in, const int* in_sizes, int n_in,
                              void* d_out, int out_size) {
    const float* inp = (const float*)d_in[0];   // [1,1,96,96] seg probs
    const float* img = (const float*)d_in[1];   // [1,3,96,96] rgb
    float* out = (float*)d_out;

    precompute_kernel<<<(NN / 2 + 255) / 256, 256>>>(inp, img, out, out_size);
    crf_main_kernel<<<NBLOCKS, TPB>>>(out);
}